// round 1
// baseline (speedup 1.0000x reference)
#include <cuda_runtime.h>
#include <cuda_bf16.h>
#include <math.h>

// Problem constants
#define BB 2
#define SS 2048
#define DD 1024
#define NH 16
#define HD 64
#define MM (BB*SS)      // 4096
#define SCALE 0.125f    // 1/sqrt(64)

// Scratch (device globals — allocation-free per harness rules)
__device__ float g_q[BB*NH*SS*HD];     // [b,n,p,h]
__device__ float g_k[BB*NH*SS*HD];
__device__ float g_v[BB*NH*SS*HD];
__device__ float g_attn[MM*DD];        // [b,p,(n,h)] = [4096,1024]

// ---------------------------------------------------------------------------
// GEMM NT: C[m,o] = sum_d A[m,d] * W[o,d]; A:[4096,1024], W:[1024,1024]
// scatter=1 -> store to [b,n,p,h] layout (for q/k/v)
// ---------------------------------------------------------------------------
__global__ __launch_bounds__(256) void gemm64_nt(
    const float* __restrict__ A, const float* __restrict__ W,
    float* __restrict__ C, int scatter)
{
    __shared__ float As[16][64];   // [k][m]
    __shared__ float Ws[16][64];   // [k][o]
    const int tid = threadIdx.x;
    const int tx = tid & 15, ty = tid >> 4;
    const int m0 = blockIdx.y * 64, n0 = blockIdx.x * 64;
    const int lr = tid >> 2;           // 0..63
    const int lc = (tid & 3) << 2;     // 0,4,8,12

    float acc[4][4];
    #pragma unroll
    for (int i = 0; i < 4; i++)
        #pragma unroll
        for (int j = 0; j < 4; j++) acc[i][j] = 0.f;

    const float* aptr = A + (size_t)(m0 + lr) * DD + lc;
    const float* wptr = W + (size_t)(n0 + lr) * DD + lc;

    for (int k0 = 0; k0 < DD; k0 += 16) {
        float4 a = *(const float4*)(aptr + k0);
        float4 w = *(const float4*)(wptr + k0);
        As[lc+0][lr] = a.x; As[lc+1][lr] = a.y; As[lc+2][lr] = a.z; As[lc+3][lr] = a.w;
        Ws[lc+0][lr] = w.x; Ws[lc+1][lr] = w.y; Ws[lc+2][lr] = w.z; Ws[lc+3][lr] = w.w;
        __syncthreads();
        #pragma unroll
        for (int k = 0; k < 16; k++) {
            float av[4], wv[4];
            #pragma unroll
            for (int i = 0; i < 4; i++) av[i] = As[k][ty*4 + i];
            #pragma unroll
            for (int j = 0; j < 4; j++) wv[j] = Ws[k][tx*4 + j];
            #pragma unroll
            for (int i = 0; i < 4; i++)
                #pragma unroll
                for (int j = 0; j < 4; j++)
                    acc[i][j] += av[i] * wv[j];
        }
        __syncthreads();
    }

    #pragma unroll
    for (int i = 0; i < 4; i++) {
        int r = m0 + ty*4 + i;
        #pragma unroll
        for (int j = 0; j < 4; j++) {
            int c = n0 + tx*4 + j;
            if (scatter) {
                int b = r >> 11, p = r & 2047;   // S=2048
                int n = c >> 6,  h = c & 63;     // HD=64
                C[(((size_t)(b*NH + n) * SS) + p) * HD + h] = acc[i][j];
            } else {
                C[(size_t)r * DD + c] = acc[i][j];
            }
        }
    }
}

// ---------------------------------------------------------------------------
// GEMM NN: C[m,d] = sum_k A[m,k] * W[k,d]; final output projection
// ---------------------------------------------------------------------------
__global__ __launch_bounds__(256) void gemm64_nn(
    const float* __restrict__ A, const float* __restrict__ W,
    float* __restrict__ C)
{
    __shared__ float As[16][64];   // [k][m]
    __shared__ float Ws[16][64];   // [k][d]
    const int tid = threadIdx.x;
    const int tx = tid & 15, ty = tid >> 4;
    const int m0 = blockIdx.y * 64, n0 = blockIdx.x * 64;
    const int lr = tid >> 2;
    const int lc = (tid & 3) << 2;
    const int wk = tid >> 4;            // 0..15
    const int wd = (tid & 15) << 2;     // 0..60

    float acc[4][4];
    #pragma unroll
    for (int i = 0; i < 4; i++)
        #pragma unroll
        for (int j = 0; j < 4; j++) acc[i][j] = 0.f;

    const float* aptr = A + (size_t)(m0 + lr) * DD + lc;

    for (int k0 = 0; k0 < DD; k0 += 16) {
        float4 a = *(const float4*)(aptr + k0);
        float4 w = *(const float4*)&W[(size_t)(k0 + wk) * DD + n0 + wd];
        As[lc+0][lr] = a.x; As[lc+1][lr] = a.y; As[lc+2][lr] = a.z; As[lc+3][lr] = a.w;
        Ws[wk][wd+0] = w.x; Ws[wk][wd+1] = w.y; Ws[wk][wd+2] = w.z; Ws[wk][wd+3] = w.w;
        __syncthreads();
        #pragma unroll
        for (int k = 0; k < 16; k++) {
            float av[4], wv[4];
            #pragma unroll
            for (int i = 0; i < 4; i++) av[i] = As[k][ty*4 + i];
            #pragma unroll
            for (int j = 0; j < 4; j++) wv[j] = Ws[k][tx*4 + j];
            #pragma unroll
            for (int i = 0; i < 4; i++)
                #pragma unroll
                for (int j = 0; j < 4; j++)
                    acc[i][j] += av[i] * wv[j];
        }
        __syncthreads();
    }

    #pragma unroll
    for (int i = 0; i < 4; i++) {
        int r = m0 + ty*4 + i;
        #pragma unroll
        for (int j = 0; j < 4; j++) {
            int c = n0 + tx*4 + j;
            C[(size_t)r * DD + c] = acc[i][j];
        }
    }
}

// ---------------------------------------------------------------------------
// Flash attention (causal), fp32. One query row per thread, 128 rows/block.
// K/V tiles of 32 keys in smem. Output written in [b,p,(n,h)] layout.
// ---------------------------------------------------------------------------
#define BQ 128
#define BK 32

__global__ __launch_bounds__(BQ) void attn_kernel(
    const float* __restrict__ q, const float* __restrict__ k,
    const float* __restrict__ v, float* __restrict__ out)
{
    __shared__ float Ks[BK * HD];          // 8 KB
    __shared__ float Vs[BK * HD];          // 8 KB
    __shared__ float Ssm[BQ * (BK + 1)];   // padded, ~16.9 KB

    const int tid = threadIdx.x;
    const int qb = blockIdx.x;     // 0..15
    const int n  = blockIdx.y;     // 0..15
    const int b  = blockIdx.z;     // 0..1
    const int qrow = qb * BQ + tid;

    const size_t head_base = (size_t)(b * NH + n) * SS * HD;

    // Load Q row into registers
    float Q[HD];
    {
        const float4* qp = (const float4*)(q + head_base + (size_t)qrow * HD);
        #pragma unroll
        for (int i = 0; i < HD/4; i++) {
            float4 t = qp[i];
            Q[4*i+0] = t.x; Q[4*i+1] = t.y; Q[4*i+2] = t.z; Q[4*i+3] = t.w;
        }
    }

    float O[HD];
    #pragma unroll
    for (int i = 0; i < HD; i++) O[i] = 0.f;
    float mrun = -1e30f, lrun = 0.f;

    const int num_tiles = (qb * BQ + BQ) / BK;   // causal bound for this block
    float* srow = &Ssm[tid * (BK + 1)];

    for (int t = 0; t < num_tiles; t++) {
        const int key0 = t * BK;
        __syncthreads();   // previous tile's PV done before overwrite
        {
            const float4* kp = (const float4*)(k + head_base + (size_t)key0 * HD);
            const float4* vp = (const float4*)(v + head_base + (size_t)key0 * HD);
            float4* ks4 = (float4*)Ks;
            float4* vs4 = (float4*)Vs;
            #pragma unroll
            for (int u = 0; u < (BK*HD/4)/BQ; u++) {   // 4 iters
                int idx = tid + u * BQ;
                ks4[idx] = kp[idx];
                vs4[idx] = vp[idx];
            }
        }
        __syncthreads();

        // QK^T for this thread's row + tile max
        float mt = mrun;
        #pragma unroll 4
        for (int j = 0; j < BK; j++) {
            float dot = 0.f;
            const float4* kr = (const float4*)&Ks[j * HD];
            #pragma unroll
            for (int i = 0; i < HD/4; i++) {
                float4 kv = kr[i];
                dot += Q[4*i+0]*kv.x + Q[4*i+1]*kv.y + Q[4*i+2]*kv.z + Q[4*i+3]*kv.w;
            }
            float s = dot * SCALE;
            if (key0 + j > qrow) s = -1e30f;
            srow[j] = s;
            mt = fmaxf(mt, s);
        }

        // rescale running state
        float corr = __expf(mrun - mt);
        lrun *= corr;
        #pragma unroll
        for (int i = 0; i < HD; i++) O[i] *= corr;

        // P·V accumulate
        #pragma unroll 2
        for (int j = 0; j < BK; j++) {
            float p = __expf(srow[j] - mt);
            lrun += p;
            const float4* vr = (const float4*)&Vs[j * HD];
            #pragma unroll
            for (int i = 0; i < HD/4; i++) {
                float4 vv = vr[i];
                O[4*i+0] += p * vv.x;
                O[4*i+1] += p * vv.y;
                O[4*i+2] += p * vv.z;
                O[4*i+3] += p * vv.w;
            }
        }
        mrun = mt;
    }

    // normalize and write to [b, p, n*64+h]
    float inv = 1.f / lrun;
    float4* op = (float4*)(out + ((size_t)(b * SS + qrow)) * DD + n * HD);
    #pragma unroll
    for (int i = 0; i < HD/4; i++) {
        float4 t;
        t.x = O[4*i+0]*inv; t.y = O[4*i+1]*inv;
        t.z = O[4*i+2]*inv; t.w = O[4*i+3]*inv;
        op[i] = t;
    }
}

// ---------------------------------------------------------------------------
extern "C" void kernel_launch(void* const* d_in, const int* in_sizes, int n_in,
                              void* d_out, int out_size)
{
    const float* residual = (const float*)d_in[0];
    const float* W_Q = (const float*)d_in[1];
    const float* W_K = (const float*)d_in[2];
    const float* W_V = (const float*)d_in[3];
    const float* W_O = (const float*)d_in[4];
    float* out = (float*)d_out;

    float *q, *kk, *vv, *attn;
    cudaGetSymbolAddress((void**)&q,    g_q);
    cudaGetSymbolAddress((void**)&kk,   g_k);
    cudaGetSymbolAddress((void**)&vv,   g_v);
    cudaGetSymbolAddress((void**)&attn, g_attn);

    dim3 ggrid(DD/64, MM/64);   // (16, 64)
    gemm64_nt<<<ggrid, 256>>>(residual, W_Q, q,    1);
    gemm64_nt<<<ggrid, 256>>>(residual, W_K, kk,   1);
    gemm64_nt<<<ggrid, 256>>>(residual, W_V, vv,   1);

    dim3 agrid(SS/BQ, NH, BB);  // (16, 16, 2)
    attn_kernel<<<agrid, BQ>>>(q, kk, vv, attn);

    gemm64_nn<<<ggrid, 256>>>(attn, W_O, out);
}

// round 3
// speedup vs baseline: 1.5396x; 1.5396x over previous
#include <cuda_runtime.h>
#include <cuda_bf16.h>
#include <cstdint>
#include <math.h>

// Problem constants
#define BB 2
#define SS 2048
#define DD 1024
#define NH 16
#define HD 64
#define MM (BB*SS)      // 4096
#define SCALE 0.125f

// ---------------------------------------------------------------------------
// Scratch (device globals)
// ---------------------------------------------------------------------------
__device__ float g_q[BB*NH*SS*HD];
__device__ float g_k[BB*NH*SS*HD];
__device__ float g_v[BB*NH*SS*HD];
__device__ float g_attn[MM*DD];
__device__ __align__(16) __nv_bfloat16 g_Ahi[MM*DD],  g_Alo[MM*DD];
__device__ __align__(16) __nv_bfloat16 g_A2hi[MM*DD], g_A2lo[MM*DD];
__device__ __align__(16) __nv_bfloat16 g_WQhi[DD*DD], g_WQlo[DD*DD];
__device__ __align__(16) __nv_bfloat16 g_WKhi[DD*DD], g_WKlo[DD*DD];
__device__ __align__(16) __nv_bfloat16 g_WVhi[DD*DD], g_WVlo[DD*DD];
__device__ __align__(16) __nv_bfloat16 g_WOhi[DD*DD], g_WOlo[DD*DD];  // transposed W_O

// ---------------------------------------------------------------------------
// helpers
// ---------------------------------------------------------------------------
__device__ __forceinline__ uint32_t smem_u32(const void* p) {
    uint32_t a;
    asm("{ .reg .u64 t; cvta.to.shared.u64 t, %1; cvt.u32.u64 %0, t; }" : "=r"(a) : "l"(p));
    return a;
}
#define LDSM_X4(r, a) asm volatile("ldmatrix.sync.aligned.m8n8.x4.shared.b16 {%0,%1,%2,%3}, [%4];" \
  : "=r"((r)[0]),"=r"((r)[1]),"=r"((r)[2]),"=r"((r)[3]) : "r"(a))
#define LDSM_X2(r, a) asm volatile("ldmatrix.sync.aligned.m8n8.x2.shared.b16 {%0,%1}, [%2];" \
  : "=r"((r)[0]),"=r"((r)[1]) : "r"(a))
#define MMA_BF16(d, a, b) asm volatile( \
  "mma.sync.aligned.m16n8k16.row.col.f32.bf16.bf16.f32 {%0,%1,%2,%3},{%4,%5,%6,%7},{%8,%9},{%0,%1,%2,%3};" \
  : "+f"((d)[0]), "+f"((d)[1]), "+f"((d)[2]), "+f"((d)[3]) \
  : "r"((a)[0]),"r"((a)[1]),"r"((a)[2]),"r"((a)[3]), "r"((b)[0]),"r"((b)[1]))
#define CP_ASYNC16(dst, src) asm volatile("cp.async.cg.shared.global [%0], [%1], 16;" :: "r"(dst), "l"(src))
#define CP_COMMIT() asm volatile("cp.async.commit_group;" ::: "memory")
#define CP_WAIT0()  asm volatile("cp.async.wait_group 0;" ::: "memory")

// ---------------------------------------------------------------------------
// split fp32 -> bf16 hi/lo (row-major, 8 elems per thread)
// ---------------------------------------------------------------------------
__global__ __launch_bounds__(256) void split2(const float* __restrict__ src,
                                              __nv_bfloat16* __restrict__ hi,
                                              __nv_bfloat16* __restrict__ lo)
{
    int idx = blockIdx.x * 256 + threadIdx.x;
    const float4* s = (const float4*)src + (size_t)idx * 2;
    float4 a0 = s[0], a1 = s[1];
    float av[8] = {a0.x, a0.y, a0.z, a0.w, a1.x, a1.y, a1.z, a1.w};
    __nv_bfloat16 h[8], l[8];
    #pragma unroll
    for (int j = 0; j < 8; j++) {
        h[j] = __float2bfloat16(av[j]);
        l[j] = __float2bfloat16(av[j] - __bfloat162float(h[j]));
    }
    ((uint4*)hi)[idx] = *(uint4*)h;
    ((uint4*)lo)[idx] = *(uint4*)l;
}

// transpose + split: out[d][o] = W[o][d]
__global__ void splitT(const float* __restrict__ W,
                       __nv_bfloat16* __restrict__ hi, __nv_bfloat16* __restrict__ lo)
{
    __shared__ float t[32][33];
    int bx = blockIdx.x * 32;   // d tile
    int by = blockIdx.y * 32;   // o tile
    int tx = threadIdx.x, ty = threadIdx.y;
    #pragma unroll
    for (int i = 0; i < 4; i++)
        t[ty + 8*i][tx] = W[(size_t)(by + ty + 8*i) * DD + bx + tx];
    __syncthreads();
    #pragma unroll
    for (int i = 0; i < 4; i++) {
        float v = t[tx][ty + 8*i];
        __nv_bfloat16 h = __float2bfloat16(v);
        __nv_bfloat16 l = __float2bfloat16(v - __bfloat162float(h));
        size_t o = (size_t)(bx + ty + 8*i) * DD + by + tx;
        hi[o] = h; lo[o] = l;
    }
}

// ---------------------------------------------------------------------------
// HMMA GEMM: C[m,o] = sum_d A[m,d]*B[o,d], 3-term split bf16, fp32 out.
// CTA 128x128, 8 warps (wm 0..3 x wn 0..1, warp tile 32x64), BK=32,
// double-buffered cp.async. grid (N/128, M/128, z)
// ---------------------------------------------------------------------------
#define ROWB 80                  // padded row stride bytes (32 bf16 + 8 pad)
#define MATB (128*ROWB)          // 10240
#define STAGEB (4*MATB)          // 40960

__global__ __launch_bounds__(256, 1) void gemm_mma(
    const __nv_bfloat16* __restrict__ Ahi, const __nv_bfloat16* __restrict__ Alo,
    const __nv_bfloat16* __restrict__ B0hi, const __nv_bfloat16* __restrict__ B0lo,
    const __nv_bfloat16* __restrict__ B1hi, const __nv_bfloat16* __restrict__ B1lo,
    const __nv_bfloat16* __restrict__ B2hi, const __nv_bfloat16* __restrict__ B2lo,
    float* __restrict__ o0, float* __restrict__ o1, float* __restrict__ o2,
    int scatter)
{
    extern __shared__ char smem[];
    const int tid = threadIdx.x, lane = tid & 31, wid = tid >> 5;
    const int wm = wid & 3, wn = wid >> 2;
    const int n0 = blockIdx.x * 128, m0 = blockIdx.y * 128, z = blockIdx.z;
    const __nv_bfloat16* Bhi = (z == 0) ? B0hi : (z == 1) ? B1hi : B2hi;
    const __nv_bfloat16* Blo = (z == 0) ? B0lo : (z == 1) ? B1lo : B2lo;
    float* out = (z == 0) ? o0 : (z == 1) ? o1 : o2;

    const __nv_bfloat16* gsrc[4] = {
        Ahi + (size_t)m0 * DD, Alo + (size_t)m0 * DD,
        Bhi + (size_t)n0 * DD, Blo + (size_t)n0 * DD };

    const uint32_t sbase = smem_u32(smem);

    // per-thread load coords (fixed across stages)
    const int lrow = tid >> 2;       // 0..63
    const int lseg = tid & 3;        // 16B segment

    float acc[2][8][4];
    #pragma unroll
    for (int t = 0; t < 2; t++)
        #pragma unroll
        for (int j = 0; j < 8; j++)
            #pragma unroll
            for (int x = 0; x < 4; x++) acc[t][j][x] = 0.f;

    // prologue: stage 0
    {
        #pragma unroll
        for (int i = 0; i < 8; i++) {
            int mat = i >> 1;
            int r = ((i & 1) << 6) | lrow;
            const __nv_bfloat16* g = gsrc[mat] + (size_t)r * DD + lseg * 8;
            CP_ASYNC16(sbase + mat * MATB + r * ROWB + lseg * 16, g);
        }
        CP_COMMIT();
    }

    for (int it = 0; it < 32; it++) {
        CP_WAIT0();
        __syncthreads();
        if (it + 1 < 32) {
            int k0 = (it + 1) * 32;
            uint32_t sb = sbase + ((it + 1) & 1) * STAGEB;
            #pragma unroll
            for (int i = 0; i < 8; i++) {
                int mat = i >> 1;
                int r = ((i & 1) << 6) | lrow;
                const __nv_bfloat16* g = gsrc[mat] + (size_t)r * DD + k0 + lseg * 8;
                CP_ASYNC16(sb + mat * MATB + r * ROWB + lseg * 16, g);
            }
            CP_COMMIT();
        }

        const uint32_t st = sbase + (it & 1) * STAGEB;
        #pragma unroll
        for (int kh = 0; kh < 2; kh++) {
            uint32_t ah[2][4], al[2][4], bh[8][2], bl[8][2];
            #pragma unroll
            for (int t = 0; t < 2; t++) {
                int row = wm * 32 + t * 16 + (lane & 15);
                uint32_t off = ((lane >> 4) * 16) + kh * 32;
                LDSM_X4(ah[t], st + 0 * MATB + row * ROWB + off);
                LDSM_X4(al[t], st + 1 * MATB + row * ROWB + off);
            }
            #pragma unroll
            for (int j = 0; j < 8; j++) {
                int row = wn * 64 + j * 8 + (lane & 7);
                uint32_t off = (((lane >> 3) & 1) * 16) + kh * 32;
                LDSM_X2(bh[j], st + 2 * MATB + row * ROWB + off);
                LDSM_X2(bl[j], st + 3 * MATB + row * ROWB + off);
            }
            #pragma unroll
            for (int t = 0; t < 2; t++)
                #pragma unroll
                for (int j = 0; j < 8; j++) {
                    MMA_BF16(acc[t][j], ah[t], bh[j]);
                    MMA_BF16(acc[t][j], ah[t], bl[j]);
                    MMA_BF16(acc[t][j], al[t], bh[j]);
                }
        }
        __syncthreads();
    }

    // epilogue
    const int r0 = lane >> 2, c0 = (lane & 3) * 2;
    #pragma unroll
    for (int t = 0; t < 2; t++) {
        #pragma unroll
        for (int j = 0; j < 8; j++) {
            int o = n0 + wn * 64 + j * 8 + c0;
            #pragma unroll
            for (int h2 = 0; h2 < 2; h2++) {
                int m = m0 + wm * 32 + t * 16 + r0 + h2 * 8;
                float2 v = make_float2(acc[t][j][2*h2], acc[t][j][2*h2+1]);
                if (scatter) {
                    int b = m >> 11, p = m & 2047;
                    int n = o >> 6, hh = o & 63;
                    *(float2*)(out + ((size_t)(b * NH + n) * SS + p) * HD + hh) = v;
                } else {
                    *(float2*)(out + (size_t)m * DD + o) = v;
                }
            }
        }
    }
}

// ---------------------------------------------------------------------------
// Flash attention (causal), fp32 — unchanged
// ---------------------------------------------------------------------------
#define BQ 128
#define BK 32

__global__ __launch_bounds__(BQ) void attn_kernel(
    const float* __restrict__ q, const float* __restrict__ k,
    const float* __restrict__ v, float* __restrict__ out)
{
    __shared__ float Ks[BK * HD];
    __shared__ float Vs[BK * HD];
    __shared__ float Ssm[BQ * (BK + 1)];

    const int tid = threadIdx.x;
    const int qb = blockIdx.x;
    const int n  = blockIdx.y;
    const int b  = blockIdx.z;
    const int qrow = qb * BQ + tid;

    const size_t head_base = (size_t)(b * NH + n) * SS * HD;

    float Q[HD];
    {
        const float4* qp = (const float4*)(q + head_base + (size_t)qrow * HD);
        #pragma unroll
        for (int i = 0; i < HD/4; i++) {
            float4 t = qp[i];
            Q[4*i+0] = t.x; Q[4*i+1] = t.y; Q[4*i+2] = t.z; Q[4*i+3] = t.w;
        }
    }

    float O[HD];
    #pragma unroll
    for (int i = 0; i < HD; i++) O[i] = 0.f;
    float mrun = -1e30f, lrun = 0.f;

    const int num_tiles = (qb * BQ + BQ) / BK;
    float* srow = &Ssm[tid * (BK + 1)];

    for (int t = 0; t < num_tiles; t++) {
        const int key0 = t * BK;
        __syncthreads();
        {
            const float4* kp = (const float4*)(k + head_base + (size_t)key0 * HD);
            const float4* vp = (const float4*)(v + head_base + (size_t)key0 * HD);
            float4* ks4 = (float4*)Ks;
            float4* vs4 = (float4*)Vs;
            #pragma unroll
            for (int u = 0; u < (BK*HD/4)/BQ; u++) {
                int idx = tid + u * BQ;
                ks4[idx] = kp[idx];
                vs4[idx] = vp[idx];
            }
        }
        __syncthreads();

        float mt = mrun;
        #pragma unroll 4
        for (int j = 0; j < BK; j++) {
            float dot = 0.f;
            const float4* kr = (const float4*)&Ks[j * HD];
            #pragma unroll
            for (int i = 0; i < HD/4; i++) {
                float4 kv = kr[i];
                dot += Q[4*i+0]*kv.x + Q[4*i+1]*kv.y + Q[4*i+2]*kv.z + Q[4*i+3]*kv.w;
            }
            float s = dot * SCALE;
            if (key0 + j > qrow) s = -1e30f;
            srow[j] = s;
            mt = fmaxf(mt, s);
        }

        float corr = __expf(mrun - mt);
        lrun *= corr;
        #pragma unroll
        for (int i = 0; i < HD; i++) O[i] *= corr;

        #pragma unroll 2
        for (int j = 0; j < BK; j++) {
            float p = __expf(srow[j] - mt);
            lrun += p;
            const float4* vr = (const float4*)&Vs[j * HD];
            #pragma unroll
            for (int i = 0; i < HD/4; i++) {
                float4 vv = vr[i];
                O[4*i+0] += p * vv.x;
                O[4*i+1] += p * vv.y;
                O[4*i+2] += p * vv.z;
                O[4*i+3] += p * vv.w;
            }
        }
        mrun = mt;
    }

    float inv = 1.f / lrun;
    float4* op = (float4*)(out + ((size_t)(b * SS + qrow)) * DD + n * HD);
    #pragma unroll
    for (int i = 0; i < HD/4; i++) {
        float4 t;
        t.x = O[4*i+0]*inv; t.y = O[4*i+1]*inv;
        t.z = O[4*i+2]*inv; t.w = O[4*i+3]*inv;
        op[i] = t;
    }
}

// ---------------------------------------------------------------------------
extern "C" void kernel_launch(void* const* d_in, const int* in_sizes, int n_in,
                              void* d_out, int out_size)
{
    const float* residual = (const float*)d_in[0];
    const float* W_Q = (const float*)d_in[1];
    const float* W_K = (const float*)d_in[2];
    const float* W_V = (const float*)d_in[3];
    const float* W_O = (const float*)d_in[4];
    float* out = (float*)d_out;

    float *q, *kk, *vv, *attn;
    __nv_bfloat16 *ahi, *alo, *a2hi, *a2lo;
    __nv_bfloat16 *wqh, *wql, *wkh, *wkl, *wvh, *wvl, *woh, *wol;
    cudaGetSymbolAddress((void**)&q,    g_q);
    cudaGetSymbolAddress((void**)&kk,   g_k);
    cudaGetSymbolAddress((void**)&vv,   g_v);
    cudaGetSymbolAddress((void**)&attn, g_attn);
    cudaGetSymbolAddress((void**)&ahi,  g_Ahi);
    cudaGetSymbolAddress((void**)&alo,  g_Alo);
    cudaGetSymbolAddress((void**)&a2hi, g_A2hi);
    cudaGetSymbolAddress((void**)&a2lo, g_A2lo);
    cudaGetSymbolAddress((void**)&wqh,  g_WQhi);
    cudaGetSymbolAddress((void**)&wql,  g_WQlo);
    cudaGetSymbolAddress((void**)&wkh,  g_WKhi);
    cudaGetSymbolAddress((void**)&wkl,  g_WKlo);
    cudaGetSymbolAddress((void**)&wvh,  g_WVhi);
    cudaGetSymbolAddress((void**)&wvl,  g_WVlo);
    cudaGetSymbolAddress((void**)&woh,  g_WOhi);
    cudaGetSymbolAddress((void**)&wol,  g_WOlo);

    const int SMEM_SZ = 2 * STAGEB;   // 81920
    cudaFuncSetAttribute(gemm_mma, cudaFuncAttributeMaxDynamicSharedMemorySize, SMEM_SZ);

    split2<<<MM*DD/8/256, 256>>>(residual, ahi, alo);
    split2<<<DD*DD/8/256, 256>>>(W_Q, wqh, wql);
    split2<<<DD*DD/8/256, 256>>>(W_K, wkh, wkl);
    split2<<<DD*DD/8/256, 256>>>(W_V, wvh, wvl);
    splitT<<<dim3(32,32), dim3(32,8)>>>(W_O, woh, wol);

    // QKV projections, scatter to [b,n,p,h]
    gemm_mma<<<dim3(8, 32, 3), 256, SMEM_SZ>>>(ahi, alo,
        wqh, wql, wkh, wkl, wvh, wvl, q, kk, vv, 1);

    // attention
    dim3 agrid(SS/BQ, NH, BB);
    attn_kernel<<<agrid, BQ>>>(q, kk, vv, attn);

    // output projection
    split2<<<MM*DD/8/256, 256>>>(attn, a2hi, a2lo);
    gemm_mma<<<dim3(8, 32, 1), 256, SMEM_SZ>>>(a2hi, a2lo,
        woh, wol, woh, wol, woh, wol, out, out, out, 0);
}

// round 4
// speedup vs baseline: 3.3726x; 2.1905x over previous
#include <cuda_runtime.h>
#include <cuda_bf16.h>
#include <cstdint>
#include <math.h>

// Problem constants
#define BB 2
#define SS 2048
#define DD 1024
#define NH 16
#define HD 64
#define MM (BB*SS)      // 4096
#define QSCALE 0.18033688011112042f   // 0.125 * log2(e)

// ---------------------------------------------------------------------------
// Scratch (device globals)
// ---------------------------------------------------------------------------
__device__ __align__(16) __nv_bfloat16 g_Ahi[MM*DD],  g_Alo[MM*DD];     // residual split
__device__ __align__(16) __nv_bfloat16 g_A2hi[MM*DD], g_A2lo[MM*DD];    // attn out split
__device__ __align__(16) __nv_bfloat16 g_WQhi[DD*DD], g_WQlo[DD*DD];
__device__ __align__(16) __nv_bfloat16 g_WKhi[DD*DD], g_WKlo[DD*DD];
__device__ __align__(16) __nv_bfloat16 g_WVhi[DD*DD], g_WVlo[DD*DD];
__device__ __align__(16) __nv_bfloat16 g_WOhi[DD*DD], g_WOlo[DD*DD];    // transposed W_O
__device__ __align__(16) __nv_bfloat16 g_Qhi[BB*NH*SS*HD], g_Qlo[BB*NH*SS*HD];
__device__ __align__(16) __nv_bfloat16 g_Khi[BB*NH*SS*HD], g_Klo[BB*NH*SS*HD];
__device__ __align__(16) __nv_bfloat16 g_Vhi[BB*NH*SS*HD], g_Vlo[BB*NH*SS*HD];

// ---------------------------------------------------------------------------
// helpers
// ---------------------------------------------------------------------------
__device__ __forceinline__ uint32_t smem_u32(const void* p) {
    uint32_t a;
    asm("{ .reg .u64 t; cvta.to.shared.u64 t, %1; cvt.u32.u64 %0, t; }" : "=r"(a) : "l"(p));
    return a;
}
#define LDSM_X4(r, a) asm volatile("ldmatrix.sync.aligned.m8n8.x4.shared.b16 {%0,%1,%2,%3}, [%4];" \
  : "=r"((r)[0]),"=r"((r)[1]),"=r"((r)[2]),"=r"((r)[3]) : "r"(a))
#define LDSM_X4T(r, a) asm volatile("ldmatrix.sync.aligned.m8n8.x4.trans.shared.b16 {%0,%1,%2,%3}, [%4];" \
  : "=r"((r)[0]),"=r"((r)[1]),"=r"((r)[2]),"=r"((r)[3]) : "r"(a))
#define LDSM_X2(r, a) asm volatile("ldmatrix.sync.aligned.m8n8.x2.shared.b16 {%0,%1}, [%2];" \
  : "=r"((r)[0]),"=r"((r)[1]) : "r"(a))
#define MMA_BF16(d, a, b) asm volatile( \
  "mma.sync.aligned.m16n8k16.row.col.f32.bf16.bf16.f32 {%0,%1,%2,%3},{%4,%5,%6,%7},{%8,%9},{%0,%1,%2,%3};" \
  : "+f"((d)[0]), "+f"((d)[1]), "+f"((d)[2]), "+f"((d)[3]) \
  : "r"((a)[0]),"r"((a)[1]),"r"((a)[2]),"r"((a)[3]), "r"((b)[0]),"r"((b)[1]))
#define CP_ASYNC16(dst, src) asm volatile("cp.async.cg.shared.global [%0], [%1], 16;" :: "r"(dst), "l"(src))
#define CP_COMMIT() asm volatile("cp.async.commit_group;" ::: "memory")
#define CP_WAIT0()  asm volatile("cp.async.wait_group 0;" ::: "memory")
#define CP_WAIT1()  asm volatile("cp.async.wait_group 1;" ::: "memory")

__device__ __forceinline__ float ex2f(float x) {
    float y; asm("ex2.approx.ftz.f32 %0, %1;" : "=f"(y) : "f"(x)); return y;
}
__device__ __forceinline__ uint32_t packbf(__nv_bfloat16 a, __nv_bfloat16 b) {
    return (uint32_t)__bfloat16_as_ushort(a) | ((uint32_t)__bfloat16_as_ushort(b) << 16);
}
// pack (x0 -> low, x1 -> high); hi = rounded bf16 pair, lo = residual pair
__device__ __forceinline__ void split_pack(float x0, float x1, uint32_t& hi, uint32_t& lo) {
    __nv_bfloat16 h0 = __float2bfloat16(x0), h1 = __float2bfloat16(x1);
    hi = packbf(h0, h1);
    __nv_bfloat16 g0 = __float2bfloat16(x0 - __bfloat162float(h0));
    __nv_bfloat16 g1 = __float2bfloat16(x1 - __bfloat162float(h1));
    lo = packbf(g0, g1);
}

// ---------------------------------------------------------------------------
// split fp32 -> bf16 hi/lo (row-major)
// ---------------------------------------------------------------------------
__global__ __launch_bounds__(256) void split2(const float* __restrict__ src,
                                              __nv_bfloat16* __restrict__ hi,
                                              __nv_bfloat16* __restrict__ lo)
{
    int idx = blockIdx.x * 256 + threadIdx.x;
    const float4* s = (const float4*)src + (size_t)idx * 2;
    float4 a0 = s[0], a1 = s[1];
    float av[8] = {a0.x, a0.y, a0.z, a0.w, a1.x, a1.y, a1.z, a1.w};
    __nv_bfloat16 h[8], l[8];
    #pragma unroll
    for (int j = 0; j < 8; j++) {
        h[j] = __float2bfloat16(av[j]);
        l[j] = __float2bfloat16(av[j] - __bfloat162float(h[j]));
    }
    ((uint4*)hi)[idx] = *(uint4*)h;
    ((uint4*)lo)[idx] = *(uint4*)l;
}

// transpose + split: out[d][o] = W[o][d]
__global__ void splitT(const float* __restrict__ W,
                       __nv_bfloat16* __restrict__ hi, __nv_bfloat16* __restrict__ lo)
{
    __shared__ float t[32][33];
    int bx = blockIdx.x * 32, by = blockIdx.y * 32;
    int tx = threadIdx.x, ty = threadIdx.y;
    #pragma unroll
    for (int i = 0; i < 4; i++)
        t[ty + 8*i][tx] = W[(size_t)(by + ty + 8*i) * DD + bx + tx];
    __syncthreads();
    #pragma unroll
    for (int i = 0; i < 4; i++) {
        float v = t[tx][ty + 8*i];
        __nv_bfloat16 h = __float2bfloat16(v);
        __nv_bfloat16 l = __float2bfloat16(v - __bfloat162float(h));
        size_t o = (size_t)(bx + ty + 8*i) * DD + by + tx;
        hi[o] = h; lo[o] = l;
    }
}

// ---------------------------------------------------------------------------
// HMMA GEMM: C[m,o] = sum_d A[m,d]*B[o,d], 3-term split bf16.
// scatter=1: write bf16 hi/lo split scattered to [b,n,p,h] (QKV path, Q scaled)
// scatter=0: write fp32 row-major (O-projection)
// ---------------------------------------------------------------------------
#define ROWB 80
#define MATB (128*ROWB)
#define STAGEB (4*MATB)

__global__ __launch_bounds__(256, 1) void gemm_mma(
    const __nv_bfloat16* __restrict__ Ahi, const __nv_bfloat16* __restrict__ Alo,
    const __nv_bfloat16* __restrict__ B0hi, const __nv_bfloat16* __restrict__ B0lo,
    const __nv_bfloat16* __restrict__ B1hi, const __nv_bfloat16* __restrict__ B1lo,
    const __nv_bfloat16* __restrict__ B2hi, const __nv_bfloat16* __restrict__ B2lo,
    float* __restrict__ of,
    __nv_bfloat16* __restrict__ s0h, __nv_bfloat16* __restrict__ s0l,
    __nv_bfloat16* __restrict__ s1h, __nv_bfloat16* __restrict__ s1l,
    __nv_bfloat16* __restrict__ s2h, __nv_bfloat16* __restrict__ s2l,
    int scatter)
{
    extern __shared__ char smem[];
    const int tid = threadIdx.x, lane = tid & 31, wid = tid >> 5;
    const int wm = wid & 3, wn = wid >> 2;
    const int n0 = blockIdx.x * 128, m0 = blockIdx.y * 128, z = blockIdx.z;
    const __nv_bfloat16* Bhi = (z == 0) ? B0hi : (z == 1) ? B1hi : B2hi;
    const __nv_bfloat16* Blo = (z == 0) ? B0lo : (z == 1) ? B1lo : B2lo;
    __nv_bfloat16* outh = (z == 0) ? s0h : (z == 1) ? s1h : s2h;
    __nv_bfloat16* outl = (z == 0) ? s0l : (z == 1) ? s1l : s2l;
    const float scalef = (scatter && z == 0) ? QSCALE : 1.0f;

    const __nv_bfloat16* gsrc[4] = {
        Ahi + (size_t)m0 * DD, Alo + (size_t)m0 * DD,
        Bhi + (size_t)n0 * DD, Blo + (size_t)n0 * DD };

    const uint32_t sbase = smem_u32(smem);
    const int lrow = tid >> 2;
    const int lseg = tid & 3;

    float acc[2][8][4];
    #pragma unroll
    for (int t = 0; t < 2; t++)
        #pragma unroll
        for (int j = 0; j < 8; j++)
            #pragma unroll
            for (int x = 0; x < 4; x++) acc[t][j][x] = 0.f;

    {
        #pragma unroll
        for (int i = 0; i < 8; i++) {
            int mat = i >> 1;
            int r = ((i & 1) << 6) | lrow;
            const __nv_bfloat16* g = gsrc[mat] + (size_t)r * DD + lseg * 8;
            CP_ASYNC16(sbase + mat * MATB + r * ROWB + lseg * 16, g);
        }
        CP_COMMIT();
    }

    for (int it = 0; it < 32; it++) {
        CP_WAIT0();
        __syncthreads();
        if (it + 1 < 32) {
            int k0 = (it + 1) * 32;
            uint32_t sb = sbase + ((it + 1) & 1) * STAGEB;
            #pragma unroll
            for (int i = 0; i < 8; i++) {
                int mat = i >> 1;
                int r = ((i & 1) << 6) | lrow;
                const __nv_bfloat16* g = gsrc[mat] + (size_t)r * DD + k0 + lseg * 8;
                CP_ASYNC16(sb + mat * MATB + r * ROWB + lseg * 16, g);
            }
            CP_COMMIT();
        }

        const uint32_t st = sbase + (it & 1) * STAGEB;
        #pragma unroll
        for (int kh = 0; kh < 2; kh++) {
            uint32_t ah[2][4], al[2][4], bh[8][2], bl[8][2];
            #pragma unroll
            for (int t = 0; t < 2; t++) {
                int row = wm * 32 + t * 16 + (lane & 15);
                uint32_t off = ((lane >> 4) * 16) + kh * 32;
                LDSM_X4(ah[t], st + 0 * MATB + row * ROWB + off);
                LDSM_X4(al[t], st + 1 * MATB + row * ROWB + off);
            }
            #pragma unroll
            for (int j = 0; j < 8; j++) {
                int row = wn * 64 + j * 8 + (lane & 7);
                uint32_t off = (((lane >> 3) & 1) * 16) + kh * 32;
                LDSM_X2(bh[j], st + 2 * MATB + row * ROWB + off);
                LDSM_X2(bl[j], st + 3 * MATB + row * ROWB + off);
            }
            #pragma unroll
            for (int t = 0; t < 2; t++)
                #pragma unroll
                for (int j = 0; j < 8; j++) {
                    MMA_BF16(acc[t][j], ah[t], bh[j]);
                    MMA_BF16(acc[t][j], ah[t], bl[j]);
                    MMA_BF16(acc[t][j], al[t], bh[j]);
                }
        }
        __syncthreads();
    }

    // epilogue
    const int r0 = lane >> 2, c0 = (lane & 3) * 2;
    #pragma unroll
    for (int t = 0; t < 2; t++) {
        #pragma unroll
        for (int j = 0; j < 8; j++) {
            int o = n0 + wn * 64 + j * 8 + c0;
            #pragma unroll
            for (int h2 = 0; h2 < 2; h2++) {
                int m = m0 + wm * 32 + t * 16 + r0 + h2 * 8;
                float x0 = acc[t][j][2*h2] * scalef, x1 = acc[t][j][2*h2+1] * scalef;
                if (scatter) {
                    int b = m >> 11, p = m & 2047;
                    int n = o >> 6, hh = o & 63;
                    size_t didx = ((size_t)(b * NH + n) * SS + p) * HD + hh;
                    uint32_t hi, lo;
                    split_pack(x0, x1, hi, lo);
                    *(uint32_t*)(outh + didx) = hi;
                    *(uint32_t*)(outl + didx) = lo;
                } else {
                    *(float2*)(of + (size_t)m * DD + o) = make_float2(x0, x1);
                }
            }
        }
    }
}

// ---------------------------------------------------------------------------
// Tensor-core flash attention (causal), split-bf16 3-term, exp2-domain softmax.
// CTA: 128 q-rows, 8 warps x 16 rows. K-tiles of 64, double-buffered.
// Writes split bf16 output in [b,p,(n,h)] layout for the O-projection GEMM.
// ---------------------------------------------------------------------------
#define AROWB 144               // 64 bf16 (128B) + 16B pad
#define AMAT  (64*AROWB)        // 9216
#define ASTG  (4*AMAT)          // 36864: Khi,Klo,Vhi,Vlo
#define AQB   (128*AROWB)       // 18432 per Q matrix

__global__ __launch_bounds__(256, 1) void attn_mma(
    const __nv_bfloat16* __restrict__ Qh, const __nv_bfloat16* __restrict__ Ql,
    const __nv_bfloat16* __restrict__ Kh, const __nv_bfloat16* __restrict__ Kl,
    const __nv_bfloat16* __restrict__ Vh, const __nv_bfloat16* __restrict__ Vl,
    __nv_bfloat16* __restrict__ Oh, __nv_bfloat16* __restrict__ Ol)
{
    extern __shared__ char smem[];
    const uint32_t sb = smem_u32(smem);
    const int tid = threadIdx.x, lane = tid & 31, wid = tid >> 5;
    const int qb = (int)gridDim.x - 1 - (int)blockIdx.x;   // long CTAs first
    const int q0 = qb * 128;
    const int n = blockIdx.y, b = blockIdx.z;
    const size_t base = (size_t)(b * NH + n) * SS * HD;
    const int nt = 2 * qb + 2;        // k-tiles (>= 2 always)
    const uint32_t ST0 = sb + 2 * AQB;

    auto load_tile = [&](int t) {
        uint32_t stb = ST0 + (uint32_t)(t & 1) * ASTG;
        int key0 = t * 64;
        const __nv_bfloat16* ms[4] = {
            Kh + base + (size_t)key0 * HD, Kl + base + (size_t)key0 * HD,
            Vh + base + (size_t)key0 * HD, Vl + base + (size_t)key0 * HD };
        #pragma unroll
        for (int mt = 0; mt < 4; mt++) {
            #pragma unroll
            for (int u = 0; u < 2; u++) {
                int idx = tid + u * 256;     // 0..511
                int row = idx >> 3, seg = idx & 7;
                CP_ASYNC16(stb + mt * AMAT + row * AROWB + seg * 16,
                           ms[mt] + (size_t)row * HD + seg * 8);
            }
        }
    };

    // Q load (group with tile 0)
    {
        const __nv_bfloat16* qs[2] = { Qh + base + (size_t)q0 * HD, Ql + base + (size_t)q0 * HD };
        #pragma unroll
        for (int mt = 0; mt < 2; mt++) {
            #pragma unroll
            for (int u = 0; u < 4; u++) {
                int idx = tid + u * 256;     // 0..1023
                int row = idx >> 3, seg = idx & 7;
                CP_ASYNC16(sb + mt * AQB + row * AROWB + seg * 16,
                           qs[mt] + (size_t)row * HD + seg * 8);
            }
        }
        load_tile(0);
        CP_COMMIT();
        load_tile(1);
        CP_COMMIT();
    }

    CP_WAIT1();
    __syncthreads();

    // Q fragments (registers, persist)
    uint32_t qfh[4][4], qfl[4][4];
    const int qw = wid * 16;
    #pragma unroll
    for (int kh = 0; kh < 4; kh++) {
        uint32_t a = sb + (qw + (lane & 15)) * AROWB + kh * 32 + (lane >> 4) * 16;
        LDSM_X4(qfh[kh], a);
        LDSM_X4(qfl[kh], a + AQB);
    }

    float m0r = -1e30f, m1r = -1e30f, l0r = 0.f, l1r = 0.f;
    float O[8][4];
    #pragma unroll
    for (int j = 0; j < 8; j++)
        #pragma unroll
        for (int x = 0; x < 4; x++) O[j][x] = 0.f;

    const int row0 = q0 + qw + (lane >> 2);   // global q row (first half)
    const int cl = (lane & 3) * 2;

    for (int it = 0; it < nt; it++) {
        const uint32_t stb = ST0 + (uint32_t)(it & 1) * ASTG;

        // ---- S = Q K^T (3-term)
        float S[8][4];
        #pragma unroll
        for (int j = 0; j < 8; j++)
            #pragma unroll
            for (int x = 0; x < 4; x++) S[j][x] = 0.f;

        #pragma unroll
        for (int kh = 0; kh < 4; kh++) {
            uint32_t kbh[4][4], kbl[4][4];
            const int g = lane >> 3, r = lane & 7;
            #pragma unroll
            for (int jp = 0; jp < 4; jp++) {
                uint32_t a = stb + (uint32_t)(((jp * 2 + (g >> 1)) * 8 + r) * AROWB + (g & 1) * 16 + kh * 32);
                LDSM_X4(kbh[jp], a);
                LDSM_X4(kbl[jp], a + AMAT);
            }
            #pragma unroll
            for (int jp = 0; jp < 4; jp++) {
                MMA_BF16(S[2*jp],   qfh[kh], kbh[jp]);
                MMA_BF16(S[2*jp],   qfh[kh], kbl[jp]);
                MMA_BF16(S[2*jp],   qfl[kh], kbh[jp]);
                MMA_BF16(S[2*jp+1], qfh[kh], kbh[jp]+2);
                MMA_BF16(S[2*jp+1], qfh[kh], kbl[jp]+2);
                MMA_BF16(S[2*jp+1], qfl[kh], kbh[jp]+2);
            }
        }

        // ---- causal mask (only near diagonal)
        if (it >= nt - 2) {
            const int kbase = it * 64 + cl;
            #pragma unroll
            for (int j = 0; j < 8; j++) {
                int c = kbase + j * 8;
                if (c     > row0)     S[j][0] = -1e30f;
                if (c + 1 > row0)     S[j][1] = -1e30f;
                if (c     > row0 + 8) S[j][2] = -1e30f;
                if (c + 1 > row0 + 8) S[j][3] = -1e30f;
            }
        }

        // ---- online softmax (log2 domain)
        float mn0 = m0r, mn1 = m1r;
        #pragma unroll
        for (int j = 0; j < 8; j++) {
            mn0 = fmaxf(mn0, fmaxf(S[j][0], S[j][1]));
            mn1 = fmaxf(mn1, fmaxf(S[j][2], S[j][3]));
        }
        mn0 = fmaxf(mn0, __shfl_xor_sync(0xffffffffu, mn0, 1));
        mn0 = fmaxf(mn0, __shfl_xor_sync(0xffffffffu, mn0, 2));
        mn1 = fmaxf(mn1, __shfl_xor_sync(0xffffffffu, mn1, 1));
        mn1 = fmaxf(mn1, __shfl_xor_sync(0xffffffffu, mn1, 2));

        float c0 = ex2f(m0r - mn0), c1 = ex2f(m1r - mn1);
        l0r *= c0; l1r *= c1;
        #pragma unroll
        for (int j = 0; j < 8; j++) {
            O[j][0] *= c0; O[j][1] *= c0; O[j][2] *= c1; O[j][3] *= c1;
        }
        m0r = mn0; m1r = mn1;

        uint32_t ph[4][4], pl[4][4];
        float s0 = 0.f, s1 = 0.f;
        #pragma unroll
        for (int j = 0; j < 8; j++) {
            float p0 = ex2f(S[j][0] - mn0), p1 = ex2f(S[j][1] - mn0);
            float p2 = ex2f(S[j][2] - mn1), p3 = ex2f(S[j][3] - mn1);
            s0 += p0 + p1; s1 += p2 + p3;
            int kk = j >> 1, i0 = (j & 1) * 2;
            split_pack(p0, p1, ph[kk][i0],   pl[kk][i0]);
            split_pack(p2, p3, ph[kk][i0+1], pl[kk][i0+1]);
        }
        s0 += __shfl_xor_sync(0xffffffffu, s0, 1);
        s0 += __shfl_xor_sync(0xffffffffu, s0, 2);
        s1 += __shfl_xor_sync(0xffffffffu, s1, 1);
        s1 += __shfl_xor_sync(0xffffffffu, s1, 2);
        l0r += s0; l1r += s1;

        // ---- O += P V (3-term)
        {
            const int g = lane >> 3, r = lane & 7;
            #pragma unroll
            for (int kk = 0; kk < 4; kk++) {
                #pragma unroll
                for (int jn = 0; jn < 4; jn++) {
                    uint32_t vbh[4], vbl[4];
                    uint32_t a = stb + 2 * AMAT
                        + (uint32_t)((kk * 16 + ((g & 1) << 3) + r) * AROWB + (2 * jn + (g >> 1)) * 16);
                    LDSM_X4T(vbh, a);
                    LDSM_X4T(vbl, a + AMAT);
                    MMA_BF16(O[2*jn],   ph[kk], vbh);
                    MMA_BF16(O[2*jn],   ph[kk], vbl);
                    MMA_BF16(O[2*jn],   pl[kk], vbh);
                    MMA_BF16(O[2*jn+1], ph[kk], vbh+2);
                    MMA_BF16(O[2*jn+1], ph[kk], vbl+2);
                    MMA_BF16(O[2*jn+1], pl[kk], vbh+2);
                }
            }
        }

        __syncthreads();   // all warps done with stage it before overwrite
        int nx = it + 2;
        if (nx < nt) { load_tile(nx); CP_COMMIT(); }
        if (it + 1 < nt) {
            if (nx < nt) CP_WAIT1(); else CP_WAIT0();
            __syncthreads();
        }
    }

    // ---- write split output: rows (b, q), cols n*64 + hd
    float inv0 = 1.f / l0r, inv1 = 1.f / l1r;
    size_t orow0 = ((size_t)(b * SS + row0)) * DD + n * HD;
    size_t orow1 = orow0 + (size_t)8 * DD;
    #pragma unroll
    for (int nb = 0; nb < 8; nb++) {
        int d = nb * 8 + cl;
        uint32_t hi, lo;
        split_pack(O[nb][0] * inv0, O[nb][1] * inv0, hi, lo);
        *(uint32_t*)(Oh + orow0 + d) = hi;
        *(uint32_t*)(Ol + orow0 + d) = lo;
        split_pack(O[nb][2] * inv1, O[nb][3] * inv1, hi, lo);
        *(uint32_t*)(Oh + orow1 + d) = hi;
        *(uint32_t*)(Ol + orow1 + d) = lo;
    }
}

// ---------------------------------------------------------------------------
extern "C" void kernel_launch(void* const* d_in, const int* in_sizes, int n_in,
                              void* d_out, int out_size)
{
    const float* residual = (const float*)d_in[0];
    const float* W_Q = (const float*)d_in[1];
    const float* W_K = (const float*)d_in[2];
    const float* W_V = (const float*)d_in[3];
    const float* W_O = (const float*)d_in[4];
    float* out = (float*)d_out;

    __nv_bfloat16 *ahi, *alo, *a2hi, *a2lo;
    __nv_bfloat16 *wqh, *wql, *wkh, *wkl, *wvh, *wvl, *woh, *wol;
    __nv_bfloat16 *qh, *ql, *kh, *kl, *vh, *vl;
    cudaGetSymbolAddress((void**)&ahi,  g_Ahi);
    cudaGetSymbolAddress((void**)&alo,  g_Alo);
    cudaGetSymbolAddress((void**)&a2hi, g_A2hi);
    cudaGetSymbolAddress((void**)&a2lo, g_A2lo);
    cudaGetSymbolAddress((void**)&wqh,  g_WQhi);
    cudaGetSymbolAddress((void**)&wql,  g_WQlo);
    cudaGetSymbolAddress((void**)&wkh,  g_WKhi);
    cudaGetSymbolAddress((void**)&wkl,  g_WKlo);
    cudaGetSymbolAddress((void**)&wvh,  g_WVhi);
    cudaGetSymbolAddress((void**)&wvl,  g_WVlo);
    cudaGetSymbolAddress((void**)&woh,  g_WOhi);
    cudaGetSymbolAddress((void**)&wol,  g_WOlo);
    cudaGetSymbolAddress((void**)&qh,   g_Qhi);
    cudaGetSymbolAddress((void**)&ql,   g_Qlo);
    cudaGetSymbolAddress((void**)&kh,   g_Khi);
    cudaGetSymbolAddress((void**)&kl,   g_Klo);
    cudaGetSymbolAddress((void**)&vh,   g_Vhi);
    cudaGetSymbolAddress((void**)&vl,   g_Vlo);

    const int GSMEM = 2 * STAGEB;                  // 81920
    const int ASMEM = 2 * AQB + 2 * ASTG;          // 110592
    cudaFuncSetAttribute(gemm_mma, cudaFuncAttributeMaxDynamicSharedMemorySize, GSMEM);
    cudaFuncSetAttribute(attn_mma, cudaFuncAttributeMaxDynamicSharedMemorySize, ASMEM);

    split2<<<MM*DD/8/256, 256>>>(residual, ahi, alo);
    split2<<<DD*DD/8/256, 256>>>(W_Q, wqh, wql);
    split2<<<DD*DD/8/256, 256>>>(W_K, wkh, wkl);
    split2<<<DD*DD/8/256, 256>>>(W_V, wvh, wvl);
    splitT<<<dim3(32,32), dim3(32,8)>>>(W_O, woh, wol);

    // QKV projections -> split bf16, scattered [b,n,p,h]; Q pre-scaled
    gemm_mma<<<dim3(8, 32, 3), 256, GSMEM>>>(ahi, alo,
        wqh, wql, wkh, wkl, wvh, wvl,
        nullptr, qh, ql, kh, kl, vh, vl, 1);

    // tensor-core flash attention -> split bf16 [b,p,(n,h)]
    attn_mma<<<dim3(SS/128, NH, BB), 256, ASMEM>>>(qh, ql, kh, kl, vh, vl, a2hi, a2lo);

    // output projection (fp32 out)
    gemm_mma<<<dim3(8, 32, 1), 256, GSMEM>>>(a2hi, a2lo,
        woh, wol, woh, wol, woh, wol,
        out, nullptr, nullptr, nullptr, nullptr, nullptr, nullptr, 0);
}